// round 1
// baseline (speedup 1.0000x reference)
#include <cuda_runtime.h>
#include <cuda_bf16.h>

#define H 2048
#define E 64
#define MAXN 16384
#define BM 64
#define BN 64
#define BK 16

// Scratch (device globals: no allocations allowed in kernel_launch)
__device__ float g_logits[(size_t)MAXN * E];        // 4 MB
__device__ float g_partial[(MAXN / 256) * E];       // per-block expert prob sums
__device__ int   g_cnt[E];                          // expert assignment counts

__global__ void init_kernel() {
    if (threadIdx.x < E) g_cnt[threadIdx.x] = 0;
}

// logits[n][e] = sum_h x[n][h] * W[e][h]
// 64x64 tile per block, 256 threads, each thread a 4x4 micro-tile, BK=16.
__global__ __launch_bounds__(256) void gemm_kernel(const float* __restrict__ x,
                                                   const float* __restrict__ W) {
    __shared__ float xs[BK][BM];
    __shared__ float ws[BK][BN];
    const int tid  = threadIdx.x;
    const int row0 = blockIdx.x * BM;
    const int tm   = (tid >> 4) * 4;   // token offset within tile
    const int tn   = (tid & 15) * 4;   // expert offset within tile
    const int lrow = tid >> 2;         // 0..63 (load row)
    const int lc   = (tid & 3) * 4;    // 0,4,8,12 (load col within BK)
    const float* xg = x + (size_t)(row0 + lrow) * H + lc;
    const float* wg = W + (size_t)lrow * H + lc;

    float acc[4][4] = {};
    for (int k0 = 0; k0 < H; k0 += BK) {
        float4 xv = *(const float4*)(xg + k0);
        float4 wv = *(const float4*)(wg + k0);
        __syncthreads();
        xs[lc + 0][lrow] = xv.x; xs[lc + 1][lrow] = xv.y;
        xs[lc + 2][lrow] = xv.z; xs[lc + 3][lrow] = xv.w;
        ws[lc + 0][lrow] = wv.x; ws[lc + 1][lrow] = wv.y;
        ws[lc + 2][lrow] = wv.z; ws[lc + 3][lrow] = wv.w;
        __syncthreads();
#pragma unroll
        for (int k = 0; k < BK; k++) {
            float4 a = *(const float4*)&xs[k][tm];
            float4 b = *(const float4*)&ws[k][tn];
            float av[4] = {a.x, a.y, a.z, a.w};
            float bv[4] = {b.x, b.y, b.z, b.w};
#pragma unroll
            for (int i = 0; i < 4; i++)
#pragma unroll
                for (int j = 0; j < 4; j++) acc[i][j] += av[i] * bv[j];
        }
    }
#pragma unroll
    for (int i = 0; i < 4; i++) {
        float4 o = make_float4(acc[i][0], acc[i][1], acc[i][2], acc[i][3]);
        *(float4*)&g_logits[(size_t)(row0 + tm + i) * E + tn] = o;
    }
}

// One thread per token: softmax over 64 experts, top-2, normalized weights,
// deterministic per-expert prob partial sums + integer counts.
__global__ __launch_bounds__(256) void softmax_kernel(float* __restrict__ out, int N) {
    const int token = blockIdx.x * 256 + threadIdx.x;
    float p[E];
    const float* lg = g_logits + (size_t)token * E;
#pragma unroll
    for (int e = 0; e < E; e += 4) {
        float4 v = *(const float4*)(lg + e);
        p[e] = v.x; p[e + 1] = v.y; p[e + 2] = v.z; p[e + 3] = v.w;
    }
    float mx = p[0];
#pragma unroll
    for (int e = 1; e < E; e++) mx = fmaxf(mx, p[e]);
    float denom = 0.f;
#pragma unroll
    for (int e = 0; e < E; e++) { p[e] = __expf(p[e] - mx); denom += p[e]; }
    const float inv = 1.f / denom;
#pragma unroll
    for (int e = 0; e < E; e++) p[e] *= inv;

    // top-2 (stable: ties keep lower index first, matching lax.top_k)
    float m1 = -1.f, m2 = -1.f;
    int i1 = 0, i2 = 0;
#pragma unroll
    for (int e = 0; e < E; e++) {
        float v = p[e];
        if (v > m1)      { m2 = m1; i2 = i1; m1 = v; i1 = e; }
        else if (v > m2) { m2 = v; i2 = e; }
    }
    const float d = m1 + m2 + 1e-6f;
    out[(size_t)token * 2 + 0] = m1 / d;
    out[(size_t)token * 2 + 1] = m2 / d;
    float* oidx = out + (size_t)2 * N;
    oidx[(size_t)token * 2 + 0] = (float)i1;
    oidx[(size_t)token * 2 + 1] = (float)i2;

    atomicAdd(&g_cnt[i1], 1);
    atomicAdd(&g_cnt[i2], 1);

    // Deterministic per-expert prob sums: warp butterfly -> smem -> fixed-order sum
    __shared__ float s_part[8][E];
    const int lane = threadIdx.x & 31;
    const int warp = threadIdx.x >> 5;
#pragma unroll
    for (int e = 0; e < E; e++) {
        float v = p[e];
        v += __shfl_xor_sync(0xffffffffu, v, 16);
        v += __shfl_xor_sync(0xffffffffu, v, 8);
        v += __shfl_xor_sync(0xffffffffu, v, 4);
        v += __shfl_xor_sync(0xffffffffu, v, 2);
        v += __shfl_xor_sync(0xffffffffu, v, 1);
        if (lane == 0) s_part[warp][e] = v;
    }
    __syncthreads();
    if (threadIdx.x < E) {
        float s = 0.f;
#pragma unroll
        for (int w = 0; w < 8; w++) s += s_part[w][threadIdx.x];
        g_partial[blockIdx.x * E + threadIdx.x] = s;
    }
}

// aux_loss = E * (sum_e pmean_e^2 + sum_e amean_e^2); also writes expert_counts.
__global__ void finalize_kernel(float* __restrict__ out, int N) {
    const int e  = threadIdx.x;   // 64 threads
    const int nb = N / 256;
    float s = 0.f;
    for (int b = 0; b < nb; b++) s += g_partial[b * E + e];
    const float pm  = s / (float)N;
    const float cnt = (float)g_cnt[e];
    const float am  = cnt / (float)N;
    float* tail = out + (size_t)4 * N;
    tail[1 + e] = cnt;
    float val = pm * pm + am * am;
    val += __shfl_xor_sync(0xffffffffu, val, 16);
    val += __shfl_xor_sync(0xffffffffu, val, 8);
    val += __shfl_xor_sync(0xffffffffu, val, 4);
    val += __shfl_xor_sync(0xffffffffu, val, 2);
    val += __shfl_xor_sync(0xffffffffu, val, 1);
    __shared__ float s2[2];
    if ((threadIdx.x & 31) == 0) s2[threadIdx.x >> 5] = val;
    __syncthreads();
    if (threadIdx.x == 0) tail[0] = (float)E * (s2[0] + s2[1]);
}

extern "C" void kernel_launch(void* const* d_in, const int* in_sizes, int n_in,
                              void* d_out, int out_size) {
    const float* x = (const float*)d_in[0];
    const float* W = (const float*)d_in[1];
    float* out = (float*)d_out;
    const int N = in_sizes[0] / H;   // 16384 tokens

    init_kernel<<<1, 64>>>();
    gemm_kernel<<<N / BM, 256>>>(x, W);
    softmax_kernel<<<N / 256, 256>>>(out, N);
    finalize_kernel<<<1, 64>>>(out, N);
}

// round 3
// speedup vs baseline: 1.5353x; 1.5353x over previous
#include <cuda_runtime.h>
#include <cuda_bf16.h>
#include <cstdint>

#define H 2048
#define E 64
#define MAXN 16384
#define TILE_M 128
#define KC 64
#define CHUNKS (H / KC)  // 32

// ---------------- device scratch ----------------
__device__ __align__(16) __nv_bfloat16 g_Wh[E * H];
__device__ __align__(16) __nv_bfloat16 g_Wm[E * H];
__device__ __align__(16) __nv_bfloat16 g_Wl[E * H];
__device__ float g_partial[(MAXN / TILE_M) * E];
__device__ int   g_cnt[E];

// ---------------- helpers ----------------
__device__ __forceinline__ uint32_t smem_u32(const void* p) {
    uint32_t a;
    asm("{ .reg .u64 t; cvta.to.shared.u64 t, %1; cvt.u32.u64 %0, t; }" : "=r"(a) : "l"(p));
    return a;
}
__device__ __forceinline__ uint32_t sw128(uint32_t o) { return o ^ ((o >> 3) & 0x70); }

__device__ __forceinline__ void split3(float v, float& h, float& m, float& l) {
    h = __bfloat162float(__float2bfloat16_rn(v));
    float r1 = v - h;
    m = __bfloat162float(__float2bfloat16_rn(r1));
    l = r1 - m;
}
__device__ __forceinline__ uint32_t packbf(float a, float b) {
    __nv_bfloat162 t = __floats2bfloat162_rn(a, b);
    return *reinterpret_cast<uint32_t*>(&t);
}

#define LDSM4(r, addr)                                                                   \
    asm volatile("ldmatrix.sync.aligned.m8n8.x4.shared.b16 {%0,%1,%2,%3}, [%4];"         \
        : "=r"((r)[0]), "=r"((r)[1]), "=r"((r)[2]), "=r"((r)[3]) : "r"(addr))

#define MMA16816(ac, a, b0, b1)                                                          \
    asm volatile("mma.sync.aligned.m16n8k16.row.col.f32.bf16.bf16.f32 "                  \
        "{%0,%1,%2,%3}, {%4,%5,%6,%7}, {%8,%9}, {%0,%1,%2,%3};"                          \
        : "+f"((ac)[0]), "+f"((ac)[1]), "+f"((ac)[2]), "+f"((ac)[3])                     \
        : "r"((a)[0]), "r"((a)[1]), "r"((a)[2]), "r"((a)[3]), "r"(b0), "r"(b1))

// ---------------- kernel 0: split W once, zero counters ----------------
__global__ __launch_bounds__(256) void prep_kernel(const float* __restrict__ W) {
    int i = blockIdx.x * 256 + threadIdx.x;
    if (i < E * H) {
        float v = W[i], h, m, l;
        split3(v, h, m, l);
        g_Wh[i] = __float2bfloat16_rn(h);
        g_Wm[i] = __float2bfloat16_rn(m);
        g_Wl[i] = __float2bfloat16_rn(l);
    }
    if (blockIdx.x == 0 && threadIdx.x < E) g_cnt[threadIdx.x] = 0;
}

// ---------------- kernel 1: fused split-bf16 HMMA GEMM + softmax/top2 ----------------
// SMEM: 2 buffers of 73728 B at offset 0:
//   A_hi/A_mid/A_lo at +0/+16384/+32768  (128 rows x 128B, swizzled)
//   B_hi/B_mid/B_lo at +49152/+57344/+65536 (64 rows x 128B, swizzled)
// s_part[4][64] at +147456. Logits overlay buf0 after mainloop (stride 65 floats).
static constexpr int A_SZ  = 16384;
static constexpr int B_SZ  = 8192;
static constexpr int B_OFF = 3 * A_SZ;           // 49152
static constexpr int BUF_SZ = B_OFF + 3 * B_SZ;  // 73728
static constexpr int OFF_SP = 2 * BUF_SZ;        // 147456
static constexpr int SMEM_TOTAL = OFF_SP + 4 * E * 4;  // 148480

__global__ __launch_bounds__(256, 1) void gemm_kernel(const float* __restrict__ x,
                                                      float* __restrict__ out, int N) {
    extern __shared__ char sdata[];
    const uint32_t sb = smem_u32(sdata);
    const int tid = threadIdx.x;
    const int wid = tid >> 5, lid = tid & 31;
    const int row0 = blockIdx.x * TILE_M;

    // loader index maps
    const int rA = tid >> 1;        // 0..127
    const int kA = (tid & 1) * 32;  // k half within chunk
    const int rB = tid >> 2;        // 0..63
    const int kB = (tid & 3) * 16;

    // ldmatrix lane maps (precomputed swizzle pieces)
    const int idx = lid >> 3;                      // 0..3
    const int a_row = wid * 16 + (idx & 1) * 8 + (lid & 7);
    const uint32_t a_rowbyte = (uint32_t)a_row * 128;
    const uint32_t a_xor = (uint32_t)(a_row & 7) << 4;
    const uint32_t a_k2 = (uint32_t)(idx >> 1) * 16;   // k_off*2
    const int b_n0 = (idx >> 1) * 8 + (lid & 7);       // n within 16-pair
    const uint32_t b_k2 = (uint32_t)(idx & 1) * 16;
    uint32_t b_rowbyte[4], b_xor[4];
#pragma unroll
    for (int j = 0; j < 4; j++) {
        int nr = j * 16 + b_n0;
        b_rowbyte[j] = (uint32_t)nr * 128;
        b_xor[j] = (uint32_t)(nr & 7) << 4;
    }

    float acc[8][4] = {};

    // prologue LDG (chunk 0)
    float4 a_raw[8];
    uint4  b_raw[3][2];
    {
        const float* xp = x + (size_t)(row0 + rA) * H + kA;
#pragma unroll
        for (int j = 0; j < 8; j++) a_raw[j] = ((const float4*)xp)[j];
        const size_t woff = (size_t)rB * H + kB;
        b_raw[0][0] = *(const uint4*)(g_Wh + woff); b_raw[0][1] = *(const uint4*)(g_Wh + woff + 8);
        b_raw[1][0] = *(const uint4*)(g_Wm + woff); b_raw[1][1] = *(const uint4*)(g_Wm + woff + 8);
        b_raw[2][0] = *(const uint4*)(g_Wl + woff); b_raw[2][1] = *(const uint4*)(g_Wl + woff + 8);
    }

    for (int c = 0; c < CHUNKS; c++) {
        char* buf = sdata + (c & 1) * BUF_SZ;
        const uint32_t sbuf = sb + (uint32_t)((c & 1) * BUF_SZ);

        // ---- STS: split A, copy B ----
#pragma unroll
        for (int g = 0; g < 4; g++) {
            float v[8] = {a_raw[2 * g].x, a_raw[2 * g].y, a_raw[2 * g].z, a_raw[2 * g].w,
                          a_raw[2 * g + 1].x, a_raw[2 * g + 1].y, a_raw[2 * g + 1].z, a_raw[2 * g + 1].w};
            uint32_t ph[4], pm[4], pl[4];
#pragma unroll
            for (int q = 0; q < 4; q++) {
                float h0, m0, l0, h1, m1, l1;
                split3(v[2 * q], h0, m0, l0);
                split3(v[2 * q + 1], h1, m1, l1);
                ph[q] = packbf(h0, h1); pm[q] = packbf(m0, m1); pl[q] = packbf(l0, l1);
            }
            uint32_t off = sw128((uint32_t)(rA * 128 + kA * 2 + g * 16));
            *(uint4*)(buf + 0 * A_SZ + off) = make_uint4(ph[0], ph[1], ph[2], ph[3]);
            *(uint4*)(buf + 1 * A_SZ + off) = make_uint4(pm[0], pm[1], pm[2], pm[3]);
            *(uint4*)(buf + 2 * A_SZ + off) = make_uint4(pl[0], pl[1], pl[2], pl[3]);
        }
        {
            uint32_t o0 = sw128((uint32_t)(rB * 128 + kB * 2));
            uint32_t o1 = sw128((uint32_t)(rB * 128 + kB * 2 + 16));
#pragma unroll
            for (int cp = 0; cp < 3; cp++) {
                *(uint4*)(buf + B_OFF + cp * B_SZ + o0) = b_raw[cp][0];
                *(uint4*)(buf + B_OFF + cp * B_SZ + o1) = b_raw[cp][1];
            }
        }
        __syncthreads();

        // ---- prefetch chunk c+1 ----
        if (c + 1 < CHUNKS) {
            const float* xp = x + (size_t)(row0 + rA) * H + (c + 1) * KC + kA;
#pragma unroll
            for (int j = 0; j < 8; j++) a_raw[j] = ((const float4*)xp)[j];
            const size_t woff = (size_t)rB * H + (c + 1) * KC + kB;
            b_raw[0][0] = *(const uint4*)(g_Wh + woff); b_raw[0][1] = *(const uint4*)(g_Wh + woff + 8);
            b_raw[1][0] = *(const uint4*)(g_Wm + woff); b_raw[1][1] = *(const uint4*)(g_Wm + woff + 8);
            b_raw[2][0] = *(const uint4*)(g_Wl + woff); b_raw[2][1] = *(const uint4*)(g_Wl + woff + 8);
        }

        // ---- MMA: 6 term-pairs, grouped by B copy ----
#pragma unroll
        for (int ks = 0; ks < 4; ks++) {
            const uint32_t kcol = (uint32_t)ks * 32;
            uint32_t Af[3][4];
#pragma unroll
            for (int cp = 0; cp < 3; cp++)
                LDSM4(Af[cp], sbuf + cp * A_SZ + a_rowbyte + ((kcol + a_k2) ^ a_xor));
#pragma unroll
            for (int bcp = 0; bcp < 3; bcp++) {
                uint32_t Bf[4][4];
#pragma unroll
                for (int j = 0; j < 4; j++)
                    LDSM4(Bf[j], sbuf + B_OFF + bcp * B_SZ + b_rowbyte[j] + ((kcol + b_k2) ^ b_xor[j]));
                const int na = (bcp == 0) ? 3 : ((bcp == 1) ? 2 : 1);
#pragma unroll
                for (int ai = 0; ai < 3; ai++) {
                    if (ai < na) {
#pragma unroll
                        for (int j = 0; j < 4; j++) {
                            MMA16816(acc[2 * j],     Af[ai], Bf[j][0], Bf[j][1]);
                            MMA16816(acc[2 * j + 1], Af[ai], Bf[j][2], Bf[j][3]);
                        }
                    }
                }
            }
        }
    }

    // ---- C frags -> smem logits (overlay buf0; last MMA read buf1) ----
    float* lg = (float*)sdata;
    {
        const int r0f = wid * 16 + (lid >> 2);
        const int c0f = (lid & 3) * 2;
#pragma unroll
        for (int nt = 0; nt < 8; nt++) {
            int col = nt * 8 + c0f;
            lg[r0f * 65 + col]           = acc[nt][0];
            lg[r0f * 65 + col + 1]       = acc[nt][1];
            lg[(r0f + 8) * 65 + col]     = acc[nt][2];
            lg[(r0f + 8) * 65 + col + 1] = acc[nt][3];
        }
    }
    __syncthreads();

    // ---- per-token softmax / top-2 / reductions (threads 0..127) ----
    float* s_part = (float*)(sdata + OFF_SP);  // [4][64]
    if (tid < 128) {
        float p[E];
#pragma unroll
        for (int e = 0; e < E; e++) p[e] = lg[tid * 65 + e];

        float mx = p[0];
#pragma unroll
        for (int e = 1; e < E; e++) mx = fmaxf(mx, p[e]);
        float denom = 0.f;
#pragma unroll
        for (int e = 0; e < E; e++) { p[e] = __expf(p[e] - mx); denom += p[e]; }
        const float inv = 1.f / denom;
#pragma unroll
        for (int e = 0; e < E; e++) p[e] *= inv;

        float m1 = -1.f, m2 = -1.f;
        int i1 = 0, i2 = 0;
#pragma unroll
        for (int e = 0; e < E; e++) {
            float v = p[e];
            if (v > m1)      { m2 = m1; i2 = i1; m1 = v; i1 = e; }
            else if (v > m2) { m2 = v; i2 = e; }
        }
        const int token = row0 + tid;
        const float d = m1 + m2 + 1e-6f;
        out[(size_t)token * 2 + 0] = m1 / d;
        out[(size_t)token * 2 + 1] = m2 / d;
        float* oidx = out + (size_t)2 * N;
        oidx[(size_t)token * 2 + 0] = (float)i1;
        oidx[(size_t)token * 2 + 1] = (float)i2;

        atomicAdd(&g_cnt[i1], 1);
        atomicAdd(&g_cnt[i2], 1);

        // deterministic per-expert prob partial sums (fixed order)
#pragma unroll
        for (int e = 0; e < E; e++) {
            float v = p[e];
            v += __shfl_xor_sync(0xffffffffu, v, 16);
            v += __shfl_xor_sync(0xffffffffu, v, 8);
            v += __shfl_xor_sync(0xffffffffu, v, 4);
            v += __shfl_xor_sync(0xffffffffu, v, 2);
            v += __shfl_xor_sync(0xffffffffu, v, 1);
            if (lid == 0) s_part[wid * E + e] = v;
        }
    }
    __syncthreads();
    if (tid < E) {
        float s = s_part[tid] + s_part[E + tid] + s_part[2 * E + tid] + s_part[3 * E + tid];
        g_partial[blockIdx.x * E + tid] = s;
    }
}

// ---------------- kernel 2: aux loss + counts ----------------
__global__ __launch_bounds__(256) void finalize_kernel(float* __restrict__ out, int N) {
    __shared__ float red[4][E];
    __shared__ float s2[2];
    const int e = threadIdx.x & 63;
    const int part = threadIdx.x >> 6;  // 0..3
    const int nb = N / TILE_M;
    float s = 0.f;
    for (int bb = part; bb < nb; bb += 4) s += g_partial[bb * E + e];
    red[part][e] = s;
    __syncthreads();
    float val = 0.f;
    if (threadIdx.x < E) {
        s = red[0][e] + red[1][e] + red[2][e] + red[3][e];
        const float pm  = s / (float)N;
        const float cnt = (float)g_cnt[e];
        const float am  = cnt / (float)N;
        out[(size_t)4 * N + 1 + e] = cnt;
        val = pm * pm + am * am;
    }
    val += __shfl_xor_sync(0xffffffffu, val, 16);
    val += __shfl_xor_sync(0xffffffffu, val, 8);
    val += __shfl_xor_sync(0xffffffffu, val, 4);
    val += __shfl_xor_sync(0xffffffffu, val, 2);
    val += __shfl_xor_sync(0xffffffffu, val, 1);
    if ((threadIdx.x & 31) == 0 && threadIdx.x < 64) s2[threadIdx.x >> 5] = val;
    __syncthreads();
    if (threadIdx.x == 0) out[(size_t)4 * N] = (float)E * (s2[0] + s2[1]);
}

extern "C" void kernel_launch(void* const* d_in, const int* in_sizes, int n_in,
                              void* d_out, int out_size) {
    const float* x = (const float*)d_in[0];
    const float* W = (const float*)d_in[1];
    float* out = (float*)d_out;
    const int N = in_sizes[0] / H;  // 16384 tokens

    cudaFuncSetAttribute(gemm_kernel, cudaFuncAttributeMaxDynamicSharedMemorySize,
                         SMEM_TOTAL);

    prep_kernel<<<(E * H + 255) / 256, 256>>>(W);
    gemm_kernel<<<N / TILE_M, 256, SMEM_TOTAL>>>(x, out, N);
    finalize_kernel<<<1, 256>>>(out, N);
}